// round 3
// baseline (speedup 1.0000x reference)
#include <cuda_runtime.h>
#include <math.h>
#include <stdint.h>

#define BB 64
#define RR 8192
#define DD 256

#define EPS_NORM 1e-12f
#define EPS_SUM  1e-8f

// ---------------- device scratch (no allocations allowed) ----------------
__device__ float    g_sims[BB * RR];   // cosine sims
__device__ int      g_idx[BB * RR];    // compacted indices (per-batch scratch)
__device__ float    g_w[BB * RR];      // compacted normalized weights
__device__ unsigned g_tick[BB];        // arrival counters (wrap to 0 each run)

__device__ __forceinline__ float sigmoid_acc(float x) {
    return 1.0f / (1.0f + expf(-x));
}

__device__ __forceinline__ int clip_q(long long qq) {
    return (int)(qq < 0 ? 0 : (qq > (RR - 1) ? (RR - 1) : qq));
}

// block reduce helpers (256 threads)
__device__ __forceinline__ float blk_sum(float v, float* s_red, int t) {
    #pragma unroll
    for (int o = 16; o > 0; o >>= 1) v += __shfl_xor_sync(0xffffffffu, v, o);
    if ((t & 31) == 0) s_red[t >> 5] = v;
    __syncthreads();
    if (t < 8) {
        float y = s_red[t];
        #pragma unroll
        for (int o = 4; o > 0; o >>= 1) y += __shfl_xor_sync(0xffu, y, o);
        if (t == 0) s_red[0] = y;
    }
    __syncthreads();
    float r = s_red[0];
    __syncthreads();
    return r;
}

// ---------------- single fused kernel ----------------
// Grid = BB * (RR/32) = 16384 blocks, 256 threads (8 warps).
// Phase 1 (all blocks): normalize query row from L2, then each warp streams
//   4 rows: copy in->out (.cs) + cosine sim via warp reduce -> g_sims.
// Phase 2 (last-arriving block per batch, via threadfence+atomicInc ticket):
//   masked softmax weights + compaction + epilogue rewrite of row q.
__global__ void __launch_bounds__(256) kFused(const float* __restrict__ in,
                                              float* __restrict__ out,
                                              const long long* __restrict__ qrels,
                                              const float* __restrict__ thrp,
                                              const float* __restrict__ strp,
                                              const float* __restrict__ scalep,
                                              const float* __restrict__ tempp)
{
    __shared__ float s_qn[DD];
    __shared__ float s_red[8];
    __shared__ int   s_ired[8];
    __shared__ unsigned s_ticket;

    const int t    = threadIdx.x;
    const int warp = t >> 5;
    const int lane = t & 31;
    const int b = blockIdx.x >> 8;                 // 256 blocks per batch
    const int rowBase = (blockIdx.x & 255) * 32;

    const int q = clip_q(qrels[b]);

    // --- per-block query-row normalization (1 KB from L2, redundant, cheap) ---
    float v = in[((size_t)b * RR + q) * DD + t];
    float nsq = blk_sum(v * v, s_red, t);
    const float invn = 1.0f / fmaxf(sqrtf(nsq), EPS_NORM);
    s_qn[t] = v * invn;
    __syncthreads();

    const float4* qn4 = (const float4*)s_qn;
    const float4 q0 = qn4[lane];
    const float4 q1 = qn4[lane + 32];

    #pragma unroll
    for (int i = 0; i < 4; i++) {
        int row = rowBase + warp * 4 + i;
        size_t off4 = ((size_t)b * RR + row) * (DD / 4);
        const float4* ip = (const float4*)in + off4;
        float4* op = (float4*)out + off4;

        float4 v0 = __ldcs(ip + lane);
        float4 v1 = __ldcs(ip + lane + 32);
        __stcs(op + lane, v0);
        __stcs(op + lane + 32, v1);

        float ss = v0.x*v0.x + v0.y*v0.y + v0.z*v0.z + v0.w*v0.w
                 + v1.x*v1.x + v1.y*v1.y + v1.z*v1.z + v1.w*v1.w;
        float dp = v0.x*q0.x + v0.y*q0.y + v0.z*q0.z + v0.w*q0.w
                 + v1.x*q1.x + v1.y*q1.y + v1.z*q1.z + v1.w*q1.w;

        #pragma unroll
        for (int o = 16; o > 0; o >>= 1) {
            ss += __shfl_xor_sync(0xffffffffu, ss, o);
            dp += __shfl_xor_sync(0xffffffffu, dp, o);
        }
        if (lane == 0) {
            float sim = dp / fmaxf(sqrtf(ss), EPS_NORM);
            g_sims[(size_t)b * RR + row] = (row == q) ? -1.0f : sim;
        }
    }

    // --- ticket: last-arriving block of this batch runs the tail ---
    __threadfence();
    __syncthreads();
    if (t == 0) s_ticket = atomicInc(&g_tick[b], 255u);  // wraps 255 -> 0
    __syncthreads();
    if (s_ticket != 255u) return;

    // ================= tail (one block per batch) =================
    const float thr      = sigmoid_acc(thrp[0]);
    const float strength = sigmoid_acc(strp[0]) * 0.2f;
    const float temp     = fminf(fmaxf(tempp[0], 0.1f), 10.0f);
    const float scale    = scalep[0];
    const float invT     = 1.0f / temp;

    const float* simsB = g_sims + (size_t)b * RR;

    // pass 1: count masked (coalesced strided loop, early exit if none)
    int cnt = 0;
    #pragma unroll 4
    for (int i = t; i < RR; i += 256)
        cnt += (simsB[i] > thr) ? 1 : 0;

    // integer block reduce
    int ctot;
    {
        int x = cnt;
        #pragma unroll
        for (int o = 16; o > 0; o >>= 1) x += __shfl_xor_sync(0xffffffffu, x, o);
        if (lane == 0) s_ired[warp] = x;
        __syncthreads();
        if (t < 8) {
            int y = s_ired[t];
            #pragma unroll
            for (int o = 4; o > 0; o >>= 1) y += __shfl_xor_sync(0xffu, y, o);
            if (t == 0) s_ired[0] = y;
        }
        __syncthreads();
        ctot = s_ired[0];
        __syncthreads();
    }
    if (ctot == 0) return;      // out row q already == qrep (copy above)

    // pass 2: fused ES (= sum e) and AS (= sum e*simw*(1+scale*s)) over masked.
    // Softmax shift not needed: s in (-1,1], s/temp <= 10 -> exp safe.
    float es = 0.0f, as = 0.0f;
    for (int i = t; i < RR; i += 256) {
        float s = simsB[i];
        if (s > thr) {
            float e  = expf(s * invT);
            float sw = 1.0f / (1.0f + expf(-(s - thr) * 10.0f));
            es += e;
            as += e * sw * (1.0f + scale * s);
        }
    }
    const float ES = blk_sum(es, s_red, t);
    const float AS = blk_sum(as, s_red, t);
    // normalized weight: a_r = e_r*w_r / (AS + eps*ES)
    const float C = 1.0f / (AS + EPS_SUM * ES);

    // offsets: warp scan + cross-warp scan of per-thread counts
    int myOff;
    {
        int inc = cnt;
        #pragma unroll
        for (int o = 1; o < 32; o <<= 1) {
            int y = __shfl_up_sync(0xffffffffu, inc, o);
            if (lane >= o) inc += y;
        }
        if (lane == 31) s_ired[warp] = inc;
        __syncthreads();
        if (t < 8) {
            int vv = s_ired[t];
            #pragma unroll
            for (int o = 1; o < 8; o <<= 1) {
                int y = __shfl_up_sync(0xffu, vv, o);
                if (t >= o) vv += y;
            }
            s_ired[t] = vv;
        }
        __syncthreads();
        int warpBase = (warp == 0) ? 0 : s_ired[warp - 1];
        myOff = warpBase + inc - cnt;
        __syncthreads();
    }

    // compaction (deterministic fixed order) into global scratch (L2-resident)
    int pos = myOff;
    for (int i = t; i < RR; i += 256) {
        float s = simsB[i];
        if (s > thr) {
            float e  = expf(s * invT);
            float sw = 1.0f / (1.0f + expf(-(s - thr) * 10.0f));
            g_idx[(size_t)b * RR + pos] = i;
            g_w [(size_t)b * RR + pos] = e * sw * (1.0f + scale * s) * C;
            pos++;
        }
    }
    __syncthreads();
    __threadfence_block();

    // epilogue: rewrite row q (t == d, DD == 256)
    float acc = 0.0f;
    for (int i = 0; i < ctot; i++) {
        int   r = g_idx[(size_t)b * RR + i];
        float w = g_w [(size_t)b * RR + i];
        acc += w * in[((size_t)b * RR + r) * DD + t];
    }
    float qv = in[((size_t)b * RR + q) * DD + t];
    out[((size_t)b * RR + q) * DD + t] = (1.0f - strength) * qv + strength * acc;
}

// ---------------- launch ----------------
extern "C" void kernel_launch(void* const* d_in, const int* in_sizes, int n_in,
                              void* d_out, int out_size)
{
    const float*     reps  = (const float*)d_in[0];
    const long long* qrels = (const long long*)d_in[1];
    const float*     thrp  = (const float*)d_in[2];
    const float*     strp  = (const float*)d_in[3];
    const float*     sclp  = (const float*)d_in[4];
    const float*     tmpp  = (const float*)d_in[5];
    float* out = (float*)d_out;

    kFused<<<BB * (RR / 32), 256>>>(reps, out, qrels, thrp, strp, sclp, tmpp);
}

// round 4
// speedup vs baseline: 1.0736x; 1.0736x over previous
#include <cuda_runtime.h>
#include <math.h>
#include <stdint.h>

#define BB 64
#define RR 8192
#define DD 256

#define EPS_NORM 1e-12f
#define EPS_SUM  1e-8f

// ---------------- device scratch (no allocations allowed) ----------------
__device__ float g_sims[BB * RR];      // cosine sims
__device__ int   g_idx[BB * RR];       // compacted indices (per-batch scratch)
__device__ float g_w[BB * RR];         // compacted normalized weights

__device__ __forceinline__ float sigmoid_acc(float x) {
    return 1.0f / (1.0f + expf(-x));
}

__device__ __forceinline__ int clip_q(long long qq) {
    return (int)(qq < 0 ? 0 : (qq > (RR - 1) ? (RR - 1) : qq));
}

// ---------------- kernel B: fused qnorm + copy + cosine sims ----------------
// (unchanged from Round 2 — best measured streaming config)
__global__ void __launch_bounds__(256) kB(const float* __restrict__ in,
                                          float* __restrict__ out,
                                          const long long* __restrict__ qrels)
{
    __shared__ float s_qn[DD];
    __shared__ float s_red[8];

    const int t    = threadIdx.x;
    const int warp = t >> 5;
    const int lane = t & 31;
    const int b = blockIdx.x >> 8;                 // 256 blocks per batch
    const int rowBase = (blockIdx.x & 255) * 32;

    const int q = clip_q(qrels[b]);

    // --- per-block query-row normalization (1 KB from L2, redundant, cheap) ---
    float v = in[((size_t)b * RR + q) * DD + t];
    float s = v * v;
    #pragma unroll
    for (int o = 16; o > 0; o >>= 1) s += __shfl_xor_sync(0xffffffffu, s, o);
    if (lane == 0) s_red[warp] = s;
    __syncthreads();
    if (t < 8) {
        float x = s_red[t];
        #pragma unroll
        for (int o = 4; o > 0; o >>= 1) x += __shfl_xor_sync(0xffu, x, o);
        if (t == 0) s_red[0] = x;
    }
    __syncthreads();
    const float invn = 1.0f / fmaxf(sqrtf(s_red[0]), EPS_NORM);
    s_qn[t] = v * invn;
    __syncthreads();

    const float4* qn4 = (const float4*)s_qn;
    const float4 q0 = qn4[lane];
    const float4 q1 = qn4[lane + 32];

    #pragma unroll
    for (int i = 0; i < 4; i++) {
        int row = rowBase + warp * 4 + i;
        size_t off4 = ((size_t)b * RR + row) * (DD / 4);
        const float4* ip = (const float4*)in + off4;
        float4* op = (float4*)out + off4;

        float4 v0 = __ldcs(ip + lane);
        float4 v1 = __ldcs(ip + lane + 32);
        __stcs(op + lane, v0);
        __stcs(op + lane + 32, v1);

        float ss = v0.x*v0.x + v0.y*v0.y + v0.z*v0.z + v0.w*v0.w
                 + v1.x*v1.x + v1.y*v1.y + v1.z*v1.z + v1.w*v1.w;
        float dp = v0.x*q0.x + v0.y*q0.y + v0.z*q0.z + v0.w*q0.w
                 + v1.x*q1.x + v1.y*q1.y + v1.z*q1.z + v1.w*q1.w;

        #pragma unroll
        for (int o = 16; o > 0; o >>= 1) {
            ss += __shfl_xor_sync(0xffffffffu, ss, o);
            dp += __shfl_xor_sync(0xffffffffu, dp, o);
        }
        if (lane == 0) {
            float sim = dp / fmaxf(sqrtf(ss), EPS_NORM);
            g_sims[(size_t)b * RR + row] = (row == q) ? -1.0f : sim;
        }
    }
}

// ---------------- kernel T: lean per-batch tail ----------------
// One block per batch, 256 threads. Reads g_sims straight from L2 (no smem
// staging), counts masked entries with early exit, then (rare path) does a
// single fused reduction + warp-shuffle scan compaction + epilogue.
__global__ void __launch_bounds__(256) kT(const float* __restrict__ in,
                                          float* __restrict__ out,
                                          const long long* __restrict__ qrels,
                                          const float* __restrict__ thrp,
                                          const float* __restrict__ strp,
                                          const float* __restrict__ scalep,
                                          const float* __restrict__ tempp)
{
    __shared__ float s_red[8];
    __shared__ int   s_ired[8];

    const int b    = blockIdx.x;
    const int t    = threadIdx.x;
    const int warp = t >> 5;
    const int lane = t & 31;

    const float thr = sigmoid_acc(thrp[0]);
    const float* __restrict__ simsB = g_sims + (size_t)b * RR;

    // pass 1: count masked entries (coalesced float4 reads, 8 KB/thr-blk iter)
    int cnt = 0;
    const float4* simsB4 = (const float4*)simsB;
    #pragma unroll
    for (int i = t; i < RR / 4; i += 256) {
        float4 s4 = __ldg(simsB4 + i);
        cnt += (s4.x > thr) + (s4.y > thr) + (s4.z > thr) + (s4.w > thr);
    }
    // block total
    int ctot;
    {
        int x = cnt;
        #pragma unroll
        for (int o = 16; o > 0; o >>= 1) x += __shfl_xor_sync(0xffffffffu, x, o);
        if (lane == 0) s_ired[warp] = x;
        __syncthreads();
        if (t < 8) {
            int y = s_ired[t];
            #pragma unroll
            for (int o = 4; o > 0; o >>= 1) y += __shfl_xor_sync(0xffu, y, o);
            if (t == 0) s_ired[0] = y;
        }
        __syncthreads();
        ctot = s_ired[0];
    }
    if (ctot == 0) return;   // out row q already == qrep (kB copy)

    // ---- rare path: mask nonempty ----
    const float strength = sigmoid_acc(strp[0]) * 0.2f;
    const float temp     = fminf(fmaxf(tempp[0], 0.1f), 10.0f);
    const float scale    = scalep[0];
    const float invT     = 1.0f / temp;
    const int   q        = clip_q(qrels[b]);

    // recount per-thread on the strided layout used below (i = t + k*256),
    // fused with ES/AS accumulation. No softmax shift needed: s <= 1.
    float es = 0.0f, as = 0.0f;
    int   mycnt = 0;
    for (int i = t; i < RR; i += 256) {
        float s = simsB[i];
        if (s > thr) {
            float e  = expf(s * invT);
            float sw = 1.0f / (1.0f + expf(-(s - thr) * 10.0f));
            es += e;
            as += e * sw * (1.0f + scale * s);
            mycnt++;
        }
    }
    // float block reduces (ES, AS)
    float ES, AS;
    {
        float x = es, y = as;
        #pragma unroll
        for (int o = 16; o > 0; o >>= 1) {
            x += __shfl_xor_sync(0xffffffffu, x, o);
            y += __shfl_xor_sync(0xffffffffu, y, o);
        }
        __syncthreads();
        if (lane == 0) { s_red[warp] = x; }
        __syncthreads();
        if (t < 8) {
            float z = s_red[t];
            #pragma unroll
            for (int o = 4; o > 0; o >>= 1) z += __shfl_xor_sync(0xffu, z, o);
            if (t == 0) s_red[0] = z;
        }
        __syncthreads();
        ES = s_red[0];
        __syncthreads();
        if (lane == 0) { s_red[warp] = y; }
        __syncthreads();
        if (t < 8) {
            float z = s_red[t];
            #pragma unroll
            for (int o = 4; o > 0; o >>= 1) z += __shfl_xor_sync(0xffu, z, o);
            if (t == 0) s_red[0] = z;
        }
        __syncthreads();
        AS = s_red[0];
    }
    // normalized weight: a_r = e_r*w_r*(1+scale*s_r) / (AS + eps*ES)
    const float C = 1.0f / (AS + EPS_SUM * ES);

    // exclusive offset: warp shuffle scan + cross-warp scan
    int myOff;
    {
        int inc = mycnt;
        #pragma unroll
        for (int o = 1; o < 32; o <<= 1) {
            int y = __shfl_up_sync(0xffffffffu, inc, o);
            if (lane >= o) inc += y;
        }
        __syncthreads();
        if (lane == 31) s_ired[warp] = inc;
        __syncthreads();
        if (t < 8) {
            int vv = s_ired[t];
            #pragma unroll
            for (int o = 1; o < 8; o <<= 1) {
                int y = __shfl_up_sync(0xffu, vv, o);
                if (t >= o) vv += y;
            }
            s_ired[t] = vv;
        }
        __syncthreads();
        int warpBase = (warp == 0) ? 0 : s_ired[warp - 1];
        myOff = warpBase + inc - mycnt;
    }

    // compaction (deterministic fixed order) into global scratch (L2-resident)
    int pos = myOff;
    for (int i = t; i < RR; i += 256) {
        float s = simsB[i];
        if (s > thr) {
            float e  = expf(s * invT);
            float sw = 1.0f / (1.0f + expf(-(s - thr) * 10.0f));
            g_idx[(size_t)b * RR + pos] = i;
            g_w [(size_t)b * RR + pos] = e * sw * (1.0f + scale * s) * C;
            pos++;
        }
    }
    __syncthreads();
    __threadfence_block();

    // epilogue: rewrite row q (t == d, DD == 256)
    float acc = 0.0f;
    for (int i = 0; i < ctot; i++) {
        int   r = g_idx[(size_t)b * RR + i];
        float w = g_w [(size_t)b * RR + i];
        acc += w * in[((size_t)b * RR + r) * DD + t];
    }
    float qv = in[((size_t)b * RR + q) * DD + t];
    out[((size_t)b * RR + q) * DD + t] = (1.0f - strength) * qv + strength * acc;
}

// ---------------- launch ----------------
extern "C" void kernel_launch(void* const* d_in, const int* in_sizes, int n_in,
                              void* d_out, int out_size)
{
    const float*     reps  = (const float*)d_in[0];
    const long long* qrels = (const long long*)d_in[1];
    const float*     thrp  = (const float*)d_in[2];
    const float*     strp  = (const float*)d_in[3];
    const float*     sclp  = (const float*)d_in[4];
    const float*     tmpp  = (const float*)d_in[5];
    float* out = (float*)d_out;

    kB<<<BB * (RR / 32), 256>>>(reps, out, qrels);
    kT<<<BB, 256>>>(reps, out, qrels, thrp, strp, sclp, tmpp);
}

// round 5
// speedup vs baseline: 1.0850x; 1.0107x over previous
#include <cuda_runtime.h>
#include <math.h>
#include <stdint.h>

#define BB 64
#define RR 8192
#define DD 256

#define EPS_NORM 1e-12f
#define EPS_SUM  1e-8f

// ---------------- device scratch (no allocations allowed) ----------------
__device__ float g_sims[BB * RR];        // cosine sims
__device__ int   g_blkcnt[BB * 256];     // per-block masked counts (plain stores)
__device__ int   g_idx[BB * RR];         // compacted indices (rare path)
__device__ float g_w[BB * RR];           // compacted normalized weights

__device__ __forceinline__ float sigmoid_acc(float x) {
    return 1.0f / (1.0f + expf(-x));
}

__device__ __forceinline__ int clip_q(long long qq) {
    return (int)(qq < 0 ? 0 : (qq > (RR - 1) ? (RR - 1) : qq));
}

// ---------------- kernel B: fused qnorm + copy + cosine sims + mask count ----
// Grid = BB * (RR/32) = 16384 blocks, 256 threads (8 warps), 4 rows/warp.
// Double-buffered loads for deeper MLP. Each block also counts its 32 rows'
// masked entries and plain-stores them to g_blkcnt[blockIdx.x].
__global__ void __launch_bounds__(256) kB(const float* __restrict__ in,
                                          float* __restrict__ out,
                                          const long long* __restrict__ qrels,
                                          const float* __restrict__ thrp)
{
    __shared__ float s_qn[DD];
    __shared__ float s_red[8];
    __shared__ int   s_icnt[8];

    const int t    = threadIdx.x;
    const int warp = t >> 5;
    const int lane = t & 31;
    const int b = blockIdx.x >> 8;                 // 256 blocks per batch
    const int rowBase = (blockIdx.x & 255) * 32;

    const int q = clip_q(qrels[b]);

    // --- per-block query-row normalization (1 KB from L2, redundant, cheap) ---
    float v = in[((size_t)b * RR + q) * DD + t];
    float s = v * v;
    #pragma unroll
    for (int o = 16; o > 0; o >>= 1) s += __shfl_xor_sync(0xffffffffu, s, o);
    if (lane == 0) s_red[warp] = s;
    __syncthreads();
    if (t < 8) {
        float x = s_red[t];
        #pragma unroll
        for (int o = 4; o > 0; o >>= 1) x += __shfl_xor_sync(0xffu, x, o);
        if (t == 0) s_red[0] = x;
    }
    __syncthreads();
    const float invn = 1.0f / fmaxf(sqrtf(s_red[0]), EPS_NORM);
    s_qn[t] = v * invn;
    __syncthreads();

    const float4* qn4 = (const float4*)s_qn;
    const float4 q0 = qn4[lane];
    const float4 q1 = qn4[lane + 32];

    const float thr = sigmoid_acc(thrp[0]);

    // base of this warp's 4 rows (rows are contiguous: warp*4 .. warp*4+3)
    const size_t base4 = ((size_t)b * RR + rowBase + warp * 4) * (DD / 4);
    const float4* ip = (const float4*)in + base4;
    float4*       op = (float4*)out + base4;

    // double-buffered streaming over 4 rows
    float4 a0 = __ldcs(ip + lane);
    float4 a1 = __ldcs(ip + lane + 32);

    int cnt = 0;
    #pragma unroll
    for (int i = 0; i < 4; i++) {
        float4 n0, n1;
        if (i < 3) {
            n0 = __ldcs(ip + (i + 1) * 64 + lane);
            n1 = __ldcs(ip + (i + 1) * 64 + lane + 32);
        }
        __stcs(op + i * 64 + lane,      a0);
        __stcs(op + i * 64 + lane + 32, a1);

        float ss = a0.x*a0.x + a0.y*a0.y + a0.z*a0.z + a0.w*a0.w
                 + a1.x*a1.x + a1.y*a1.y + a1.z*a1.z + a1.w*a1.w;
        float dp = a0.x*q0.x + a0.y*q0.y + a0.z*q0.z + a0.w*q0.w
                 + a1.x*q1.x + a1.y*q1.y + a1.z*q1.z + a1.w*q1.w;

        #pragma unroll
        for (int o = 16; o > 0; o >>= 1) {
            ss += __shfl_xor_sync(0xffffffffu, ss, o);
            dp += __shfl_xor_sync(0xffffffffu, dp, o);
        }
        const int row = rowBase + warp * 4 + i;
        float sim = dp / fmaxf(sqrtf(ss), EPS_NORM);
        sim = (row == q) ? -1.0f : sim;        // all lanes hold full sums
        if (lane == 0) g_sims[(size_t)b * RR + row] = sim;
        cnt += (sim > thr) ? 1 : 0;

        a0 = n0; a1 = n1;
    }

    if (lane == 0) s_icnt[warp] = cnt;
    __syncthreads();
    if (t == 0) {
        int c = 0;
        #pragma unroll
        for (int w = 0; w < 8; w++) c += s_icnt[w];
        g_blkcnt[blockIdx.x] = c;   // plain store: deterministic, replay-safe
    }
}

// ---------------- kernel T: per-batch tail (cheap common path) ----------------
// One block per batch, 256 threads. Common path: sum 256 per-block counts
// (1 KB from L2) and exit if zero. Rare path: full masked-softmax + epilogue.
__global__ void __launch_bounds__(256) kT(const float* __restrict__ in,
                                          float* __restrict__ out,
                                          const long long* __restrict__ qrels,
                                          const float* __restrict__ thrp,
                                          const float* __restrict__ strp,
                                          const float* __restrict__ scalep,
                                          const float* __restrict__ tempp)
{
    __shared__ float s_red[8];
    __shared__ int   s_ired[8];

    const int b    = blockIdx.x;
    const int t    = threadIdx.x;
    const int warp = t >> 5;
    const int lane = t & 31;

    // --- common path: reduce per-block counts ---
    int cnt = g_blkcnt[b * 256 + t];
    int ctot;
    {
        int x = cnt;
        #pragma unroll
        for (int o = 16; o > 0; o >>= 1) x += __shfl_xor_sync(0xffffffffu, x, o);
        if (lane == 0) s_ired[warp] = x;
        __syncthreads();
        if (t < 8) {
            int y = s_ired[t];
            #pragma unroll
            for (int o = 4; o > 0; o >>= 1) y += __shfl_xor_sync(0xffu, y, o);
            if (t == 0) s_ired[0] = y;
        }
        __syncthreads();
        ctot = s_ired[0];
    }
    if (ctot == 0) return;   // out row q already == qrep (kB copy)

    // ================= rare path: mask nonempty =================
    const float thr      = sigmoid_acc(thrp[0]);
    const float strength = sigmoid_acc(strp[0]) * 0.2f;
    const float temp     = fminf(fmaxf(tempp[0], 0.1f), 10.0f);
    const float scale    = scalep[0];
    const float invT     = 1.0f / temp;
    const int   q        = clip_q(qrels[b]);

    const float* __restrict__ simsB = g_sims + (size_t)b * RR;

    // fused ES/AS + per-thread count on the strided layout (i = t + k*256).
    // No softmax shift needed: s <= 1 -> exp(s/temp) <= e^10, safe.
    float es = 0.0f, as = 0.0f;
    int   mycnt = 0;
    for (int i = t; i < RR; i += 256) {
        float s = simsB[i];
        if (s > thr) {
            float e  = expf(s * invT);
            float sw = 1.0f / (1.0f + expf(-(s - thr) * 10.0f));
            es += e;
            as += e * sw * (1.0f + scale * s);
            mycnt++;
        }
    }
    float ES, AS;
    {
        float x = es, y = as;
        #pragma unroll
        for (int o = 16; o > 0; o >>= 1) {
            x += __shfl_xor_sync(0xffffffffu, x, o);
            y += __shfl_xor_sync(0xffffffffu, y, o);
        }
        __syncthreads();
        if (lane == 0) s_red[warp] = x;
        __syncthreads();
        if (t < 8) {
            float z = s_red[t];
            #pragma unroll
            for (int o = 4; o > 0; o >>= 1) z += __shfl_xor_sync(0xffu, z, o);
            if (t == 0) s_red[0] = z;
        }
        __syncthreads();
        ES = s_red[0];
        __syncthreads();
        if (lane == 0) s_red[warp] = y;
        __syncthreads();
        if (t < 8) {
            float z = s_red[t];
            #pragma unroll
            for (int o = 4; o > 0; o >>= 1) z += __shfl_xor_sync(0xffu, z, o);
            if (t == 0) s_red[0] = z;
        }
        __syncthreads();
        AS = s_red[0];
    }
    // normalized weight: a_r = e_r*w_r*(1+scale*s_r) / (AS + eps*ES)
    const float C = 1.0f / (AS + EPS_SUM * ES);

    // exclusive offset: warp shuffle scan + cross-warp scan
    int myOff;
    {
        int inc = mycnt;
        #pragma unroll
        for (int o = 1; o < 32; o <<= 1) {
            int y = __shfl_up_sync(0xffffffffu, inc, o);
            if (lane >= o) inc += y;
        }
        __syncthreads();
        if (lane == 31) s_ired[warp] = inc;
        __syncthreads();
        if (t < 8) {
            int vv = s_ired[t];
            #pragma unroll
            for (int o = 1; o < 8; o <<= 1) {
                int y = __shfl_up_sync(0xffu, vv, o);
                if (t >= o) vv += y;
            }
            s_ired[t] = vv;
        }
        __syncthreads();
        int warpBase = (warp == 0) ? 0 : s_ired[warp - 1];
        myOff = warpBase + inc - mycnt;
    }

    // compaction (deterministic fixed order) into global scratch (L2-resident)
    int pos = myOff;
    for (int i = t; i < RR; i += 256) {
        float s = simsB[i];
        if (s > thr) {
            float e  = expf(s * invT);
            float sw = 1.0f / (1.0f + expf(-(s - thr) * 10.0f));
            g_idx[(size_t)b * RR + pos] = i;
            g_w [(size_t)b * RR + pos] = e * sw * (1.0f + scale * s) * C;
            pos++;
        }
    }
    __syncthreads();
    __threadfence_block();

    // epilogue: rewrite row q (t == d, DD == 256)
    float acc = 0.0f;
    for (int i = 0; i < ctot; i++) {
        int   r = g_idx[(size_t)b * RR + i];
        float w = g_w [(size_t)b * RR + i];
        acc += w * in[((size_t)b * RR + r) * DD + t];
    }
    float qv = in[((size_t)b * RR + q) * DD + t];
    out[((size_t)b * RR + q) * DD + t] = (1.0f - strength) * qv + strength * acc;
}

// ---------------- launch ----------------
extern "C" void kernel_launch(void* const* d_in, const int* in_sizes, int n_in,
                              void* d_out, int out_size)
{
    const float*     reps  = (const float*)d_in[0];
    const long long* qrels = (const long long*)d_in[1];
    const float*     thrp  = (const float*)d_in[2];
    const float*     strp  = (const float*)d_in[3];
    const float*     sclp  = (const float*)d_in[4];
    const float*     tmpp  = (const float*)d_in[5];
    float* out = (float*)d_out;

    kB<<<BB * (RR / 32), 256>>>(reps, out, qrels, thrp);
    kT<<<BB, 256>>>(reps, out, qrels, thrp, strp, sclp, tmpp);
}